// round 4
// baseline (speedup 1.0000x reference)
#include <cuda_runtime.h>
#include <math.h>

#define NN 12288
#define EE 196608
#define FF 128

// ---------------- static device scratch ----------------
__device__ int   g_deg[NN];
__device__ int   g_off[NN];
__device__ int   g_cur[NN];
__device__ int   g_src_by_dst[EE];
__device__ int   g_bk_cnt[64];
__device__ int   g_bk_off[64];
__device__ int   g_bk_cur[64];
__device__ int   g_eb_src[EE];
__device__ int   g_eb_dst[EE];
__device__ float g_agg[NN * FF];
__device__ float g_lin[NN * 384];
__device__ float g_embed[NN * FF];
__device__ float g_result[NN * 32];
__device__ float g_G[8 * 32 * 32];
__device__ unsigned int g_sumA2;

// ---------------- helpers ----------------
__device__ __forceinline__ float wsum(float v) {
    #pragma unroll
    for (int o = 16; o; o >>= 1) v += __shfl_xor_sync(0xffffffffu, v, o);
    return v;
}
__device__ __forceinline__ float wmax(float v) {
    #pragma unroll
    for (int o = 16; o; o >>= 1) v = fmaxf(v, __shfl_xor_sync(0xffffffffu, v, o));
    return v;
}
__device__ __forceinline__ int lbound(const int* b, int v) {
    int lo = 0, hi = NN;
    while (lo < hi) { int m = (lo + hi) >> 1; if (b[m] < v) lo = m + 1; else hi = m; }
    return lo;
}

// ---------------- K1: zero init ----------------
__global__ void k_init(float* out) {
    int i = blockIdx.x * 256 + threadIdx.x;
    if (i < 98304) out[i] = 0.f;            // adj_new (65536) + h (32768)
    if (i < NN) g_deg[i] = 0;
    if (i < 64) g_bk_cnt[i] = 0;
    if (i < 8192) g_G[i] = 0.f;
    if (i == 0) g_sumA2 = 0u;
}

// ---------------- K2: histograms ----------------
__global__ void k_hist(const int* __restrict__ ei, const int* __restrict__ batch) {
    int i = blockIdx.x * 256 + threadIdx.x;
    if (i < EE) {
        int s = ei[i], d = ei[EE + i];
        atomicAdd(&g_deg[d], 1);
        atomicAdd(&g_bk_cnt[batch[s] * 8 + batch[d]], 1);
    }
}

// ---------------- K3: exclusive scans (single block) ----------------
__global__ void k_scan() {
    __shared__ int part[1024];
    int t = threadIdx.x;
    int base = t * 12;
    int loc[12]; int s = 0;
    #pragma unroll
    for (int i = 0; i < 12; i++) { loc[i] = s; s += g_deg[base + i]; }
    part[t] = s;
    __syncthreads();
    for (int d = 1; d < 1024; d <<= 1) {
        int v = (t >= d) ? part[t - d] : 0;
        __syncthreads();
        part[t] += v;
        __syncthreads();
    }
    int pre = t ? part[t - 1] : 0;
    #pragma unroll
    for (int i = 0; i < 12; i++) {
        int o = pre + loc[i];
        g_off[base + i] = o;
        g_cur[base + i] = o;
    }
    if (t == 0) {
        int acc = 0;
        for (int k = 0; k < 64; k++) {
            g_bk_off[k] = acc; g_bk_cur[k] = acc; acc += g_bk_cnt[k];
        }
    }
}

// ---------------- K4: scatter into dst-CSR and edge buckets ----------------
__global__ void k_scatter(const int* __restrict__ ei, const int* __restrict__ batch) {
    int i = blockIdx.x * 256 + threadIdx.x;
    if (i < EE) {
        int s = ei[i], d = ei[EE + i];
        int p = atomicAdd(&g_cur[d], 1);
        g_src_by_dst[p] = s;
        int q = atomicAdd(&g_bk_cur[batch[s] * 8 + batch[d]], 1);
        g_eb_src[q] = s;
        g_eb_dst[q] = d;
    }
}

// ---------------- K5: mean aggregation (warp per dst node) ----------------
__global__ __launch_bounds__(256) void k_agg(const float* __restrict__ x) {
    int t = threadIdx.x, w = t >> 5, lane = t & 31;
    int n = blockIdx.x * 8 + w;
    int e0 = g_off[n], deg = g_deg[n];
    float4 a = make_float4(0.f, 0.f, 0.f, 0.f);
    for (int e = e0; e < e0 + deg; e++) {
        int s = g_src_by_dst[e];
        float4 v = *(const float4*)(x + (size_t)s * FF + lane * 4);
        a.x += v.x; a.y += v.y; a.z += v.z; a.w += v.w;
    }
    float inv = 1.f / fmaxf((float)deg, 1.f);
    a.x *= inv; a.y *= inv; a.z *= inv; a.w *= inv;
    *(float4*)(g_agg + (size_t)n * FF + lane * 4) = a;
}

// ---------------- K6: GEMM  [N x 256] @ [256 x 384]  (A = [x | agg]) ----------------
__global__ __launch_bounds__(256) void k_gemm(const float* __restrict__ x,
                                              const float* __restrict__ Wembd,
                                              const float* __restrict__ Wpool) {
    __shared__ float As[16][64];
    __shared__ float Bs[16][64];
    int t = threadIdx.x;
    int row0 = blockIdx.x * 64;
    int col0 = blockIdx.y * 64;
    int tm = t >> 4, tn = t & 15;
    float acc[4][4];
    #pragma unroll
    for (int i = 0; i < 4; i++)
        #pragma unroll
        for (int j = 0; j < 4; j++) acc[i][j] = 0.f;

    for (int kc = 0; kc < 256; kc += 16) {
        {
            int r = t >> 2;
            int kq = (t & 3) * 4;
            const float* Asrc = (kc < 128) ? x : g_agg;
            int kk = kc & 127;
            float4 v = *(const float4*)(Asrc + (size_t)(row0 + r) * FF + kk + kq);
            As[kq + 0][r] = v.x; As[kq + 1][r] = v.y;
            As[kq + 2][r] = v.z; As[kq + 3][r] = v.w;
        }
        {
            int kr = t >> 4;
            int nq = (t & 15) * 4;
            int c = col0 + nq;
            float4 v;
            if (c < 128) v = *(const float4*)(Wembd + (size_t)(kc + kr) * 128 + c);
            else         v = *(const float4*)(Wpool + (size_t)(kc + kr) * 256 + (c - 128));
            *(float4*)&Bs[kr][nq] = v;
        }
        __syncthreads();
        #pragma unroll
        for (int k = 0; k < 16; k++) {
            float4 a = *(const float4*)&As[k][tm * 4];
            float4 b = *(const float4*)&Bs[k][tn * 4];
            acc[0][0] += a.x * b.x; acc[0][1] += a.x * b.y; acc[0][2] += a.x * b.z; acc[0][3] += a.x * b.w;
            acc[1][0] += a.y * b.x; acc[1][1] += a.y * b.y; acc[1][2] += a.y * b.z; acc[1][3] += a.y * b.w;
            acc[2][0] += a.z * b.x; acc[2][1] += a.z * b.y; acc[2][2] += a.z * b.z; acc[2][3] += a.z * b.w;
            acc[3][0] += a.w * b.x; acc[3][1] += a.w * b.y; acc[3][2] += a.w * b.z; acc[3][3] += a.w * b.w;
        }
        __syncthreads();
    }
    #pragma unroll
    for (int i = 0; i < 4; i++) {
        float4 o = make_float4(acc[i][0], acc[i][1], acc[i][2], acc[i][3]);
        *(float4*)(g_lin + (size_t)(row0 + tm * 4 + i) * 384 + col0 + tn * 4) = o;
    }
}

// ---------------- K7: bias + L2-normalize + block softmax (warp per node) ----------------
__global__ __launch_bounds__(256) void k_epi(const float* __restrict__ bembd,
                                             const float* __restrict__ bpool,
                                             const int* __restrict__ batch) {
    __shared__ float sblk[8][32];
    int t = threadIdx.x, w = t >> 5, lane = t & 31;
    int n = blockIdx.x * 8 + w;
    const float* L = g_lin + (size_t)n * 384;

    // embed part (lin cols 0..127)
    float4 v = *(const float4*)(L + lane * 4);
    float4 be = *(const float4*)(bembd + lane * 4);
    v.x += be.x; v.y += be.y; v.z += be.z; v.w += be.w;
    float ss = wsum(v.x * v.x + v.y * v.y + v.z * v.z + v.w * v.w);
    float inv = 1.f / fmaxf(sqrtf(ss), 1e-12f);
    float4 e4 = make_float4(v.x * inv, v.y * inv, v.z * inv, v.w * inv);
    *(float4*)(g_embed + (size_t)n * FF + lane * 4) = e4;

    // pool part (lin cols 128..383): lane holds pooled cols [lane*8, lane*8+8)
    float4 p0 = *(const float4*)(L + 128 + lane * 8);
    float4 p1 = *(const float4*)(L + 128 + lane * 8 + 4);
    float4 b0 = *(const float4*)(bpool + lane * 8);
    float4 b1 = *(const float4*)(bpool + lane * 8 + 4);
    p0.x += b0.x; p0.y += b0.y; p0.z += b0.z; p0.w += b0.w;
    p1.x += b1.x; p1.y += b1.y; p1.z += b1.z; p1.w += b1.w;
    float ss2 = wsum(p0.x * p0.x + p0.y * p0.y + p0.z * p0.z + p0.w * p0.w +
                     p1.x * p1.x + p1.y * p1.y + p1.z * p1.z + p1.w * p1.w);
    float inv2 = 1.f / fmaxf(sqrtf(ss2), 1e-12f);

    int g = batch[n];
    if ((lane >> 2) == g) {
        int off = (lane & 3) * 8;
        sblk[w][off + 0] = p0.x * inv2; sblk[w][off + 1] = p0.y * inv2;
        sblk[w][off + 2] = p0.z * inv2; sblk[w][off + 3] = p0.w * inv2;
        sblk[w][off + 4] = p1.x * inv2; sblk[w][off + 5] = p1.y * inv2;
        sblk[w][off + 6] = p1.z * inv2; sblk[w][off + 7] = p1.w * inv2;
    }
    __syncwarp();
    float m = sblk[w][lane];
    float mx = wmax(m);
    float e = __expf(m - mx);
    float s = wsum(e);
    g_result[(size_t)n * 32 + lane] = e / s;
}

// ---------------- K8: adj_new = sum_edges outer(S[src], S[dst]) ----------------
__global__ __launch_bounds__(256) void k_adj(float* out) {
    int b = blockIdx.x;
    int s0 = g_bk_off[b];
    int s1 = (b == 63) ? EE : g_bk_off[b + 1];
    int len = s1 - s0;
    int per = (len + 7) / 8;
    int e0 = s0 + blockIdx.y * per;
    int e1 = min(e0 + per, s1);
    __shared__ float Sa[8][32];
    __shared__ float Sb[8][32];
    int t = threadIdx.x;
    int i = t >> 3, j0 = (t & 7) * 4;
    float4 acc = make_float4(0.f, 0.f, 0.f, 0.f);
    for (int base = e0; base < e1; base += 8) {
        int ne = min(8, e1 - base);
        if ((t >> 5) < ne) {
            int e = base + (t >> 5);
            int l = t & 31;
            Sa[t >> 5][l] = g_result[(size_t)g_eb_src[e] * 32 + l];
            Sb[t >> 5][l] = g_result[(size_t)g_eb_dst[e] * 32 + l];
        }
        __syncthreads();
        for (int jj = 0; jj < ne; jj++) {
            float a = Sa[jj][i];
            float4 bv = *(const float4*)&Sb[jj][j0];
            acc.x += a * bv.x; acc.y += a * bv.y;
            acc.z += a * bv.z; acc.w += a * bv.w;
        }
        __syncthreads();
    }
    if (e0 < e1) {
        int gs = b >> 3, gd = b & 7;
        float* dst = out + (size_t)(gs * 32 + i) * 256 + gd * 32 + j0;
        atomicAdd(dst + 0, acc.x); atomicAdd(dst + 1, acc.y);
        atomicAdd(dst + 2, acc.z); atomicAdd(dst + 3, acc.w);
    }
}

// ---------------- K9: h = S^T E  and  G = S^T S  (per graph) ----------------
__global__ __launch_bounds__(256) void k_pool(const int* __restrict__ batch, float* out) {
    __shared__ float Ms[4][160];
    __shared__ int srange[2];
    int g = blockIdx.x;
    int t = threadIdx.x;
    if (t == 0) { srange[0] = lbound(batch, g); srange[1] = lbound(batch, g + 1); }
    __syncthreads();
    int n0 = srange[0], n1 = srange[1];
    int len = n1 - n0;
    int per = (len + 15) / 16;
    int m0 = n0 + blockIdx.y * per;
    int m1 = min(m0 + per, n1);

    int i = t >> 3, j0 = (t & 7) * 4;
    float4 acc[5];
    #pragma unroll
    for (int b = 0; b < 5; b++) acc[b] = make_float4(0.f, 0.f, 0.f, 0.f);

    for (int base = m0; base < m1; base += 4) {
        int nn = min(4, m1 - base);
        for (int idx = t; idx < nn * 160; idx += 256) {
            int j = idx / 160, c = idx % 160;
            int n = base + j;
            Ms[j][c] = (c < 128) ? g_embed[(size_t)n * 128 + c]
                                 : g_result[(size_t)n * 32 + (c - 128)];
        }
        __syncthreads();
        for (int jj = 0; jj < nn; jj++) {
            float a = Ms[jj][128 + i];
            #pragma unroll
            for (int b = 0; b < 5; b++) {
                float4 v = *(const float4*)&Ms[jj][j0 + 32 * b];
                acc[b].x += a * v.x; acc[b].y += a * v.y;
                acc[b].z += a * v.z; acc[b].w += a * v.w;
            }
        }
        __syncthreads();
    }
    if (m0 < m1) {
        #pragma unroll
        for (int b = 0; b < 4; b++) {
            float* dst = out + 65536 + (size_t)(g * 32 + i) * 128 + j0 + 32 * b;
            atomicAdd(dst + 0, acc[b].x); atomicAdd(dst + 1, acc[b].y);
            atomicAdd(dst + 2, acc[b].z); atomicAdd(dst + 3, acc[b].w);
        }
        float* dg = g_G + (size_t)g * 1024 + i * 32 + j0;
        atomicAdd(dg + 0, acc[4].x); atomicAdd(dg + 1, acc[4].y);
        atomicAdd(dg + 2, acc[4].z); atomicAdd(dg + 3, acc[4].w);
    }
}

// ---------------- K10: sum of squared edge multiplicities (exact, int) ----------------
__global__ void k_dup() {
    int n = blockIdx.x * 256 + threadIdx.x;
    int cnt = 0;
    if (n < NN) {
        int o = g_off[n], L = g_deg[n];
        for (int ii = 0; ii < L; ii++) {
            int si = g_src_by_dst[o + ii];
            for (int jj = 0; jj < L; jj++) cnt += (g_src_by_dst[o + jj] == si);
        }
    }
    #pragma unroll
    for (int off = 16; off; off >>= 1) cnt += __shfl_xor_sync(0xffffffffu, cnt, off);
    if ((threadIdx.x & 31) == 0) atomicAdd(&g_sumA2, (unsigned int)cnt);
}

// ---------------- K11: finalize losses ----------------
__global__ void k_final(float* out) {
    __shared__ float red[256];
    int t = threadIdx.x;
    // trace(adj_new)
    float v = out[(size_t)t * 257];
    red[t] = v;
    __syncthreads();
    for (int s = 128; s; s >>= 1) { if (t < s) red[t] += red[t + s]; __syncthreads(); }
    float tr = red[0];
    __syncthreads();
    // ||G||_F^2
    float gq = 0.f;
    for (int i = t; i < 8192; i += 256) { float g = g_G[i]; gq += g * g; }
    red[t] = gq;
    __syncthreads();
    for (int s = 128; s; s >>= 1) { if (t < s) red[t] += red[t + s]; __syncthreads(); }
    if (t == 0) {
        float a2 = (float)g_sumA2;
        float val = a2 - 2.f * tr + red[0];
        out[98304] = sqrtf(fmaxf(val, 0.f)) / 150994944.0f;   // / N^2
        out[98305] = 12288.0f * logf(32.0f);
    }
}

// ---------------- launch ----------------
extern "C" void kernel_launch(void* const* d_in, const int* in_sizes, int n_in,
                              void* d_out, int out_size) {
    const float* x     = (const float*)d_in[0];
    const int*   ei    = (const int*)d_in[1];
    const int*   batch = (const int*)d_in[2];
    const float* Wembd = (const float*)d_in[3];
    const float* bembd = (const float*)d_in[4];
    const float* Wpool = (const float*)d_in[5];
    const float* bpool = (const float*)d_in[6];
    float* out = (float*)d_out;

    k_init<<<384, 256>>>(out);
    k_hist<<<768, 256>>>(ei, batch);
    k_scan<<<1, 1024>>>();
    k_scatter<<<768, 256>>>(ei, batch);
    k_agg<<<1536, 256>>>(x);
    k_gemm<<<dim3(192, 6), 256>>>(x, Wembd, Wpool);
    k_epi<<<1536, 256>>>(bembd, bpool, batch);
    k_adj<<<dim3(64, 8), 256>>>(out);
    k_pool<<<dim3(8, 16), 256>>>(batch, out);
    k_dup<<<48, 256>>>();
    k_final<<<1, 256>>>(out);
}

// round 5
// speedup vs baseline: 1.7128x; 1.7128x over previous
#include <cuda_runtime.h>
#include <math.h>

#define NN 12288
#define EE 196608
#define FF 128

// ---------------- static device scratch ----------------
__device__ int   g_deg[NN];
__device__ int   g_off[NN];
__device__ int   g_cur[NN];
__device__ int   g_src_by_dst[EE];
__device__ int   g_bk_cnt[64];
__device__ int   g_bk_off[64];
__device__ int   g_bk_cur[64];
__device__ int   g_eb_src[EE];
__device__ int   g_eb_dst[EE];
__device__ float g_agg[NN * FF];
__device__ float g_lin[NN * 384];
__device__ float g_embed[NN * FF];
__device__ float g_result[NN * 32];
__device__ float g_G[8 * 32 * 32];
__device__ unsigned int g_sumA2;

// ---------------- helpers ----------------
__device__ __forceinline__ float wsum(float v) {
    #pragma unroll
    for (int o = 16; o; o >>= 1) v += __shfl_xor_sync(0xffffffffu, v, o);
    return v;
}
__device__ __forceinline__ float wmax(float v) {
    #pragma unroll
    for (int o = 16; o; o >>= 1) v = fmaxf(v, __shfl_xor_sync(0xffffffffu, v, o));
    return v;
}
__device__ __forceinline__ int lbound(const int* b, int v) {
    int lo = 0, hi = NN;
    while (lo < hi) { int m = (lo + hi) >> 1; if (b[m] < v) lo = m + 1; else hi = m; }
    return lo;
}
// packed f32x2 FMA: c += a * b (elementwise on two packed floats)
__device__ __forceinline__ void ffma2(unsigned long long &c, unsigned long long a,
                                      unsigned long long b) {
    asm("fma.rn.f32x2 %0, %1, %2, %0;" : "+l"(c) : "l"(a), "l"(b));
}
__device__ __forceinline__ unsigned long long pkdup(float a) {
    unsigned long long r;
    asm("mov.b64 %0, {%1, %1};" : "=l"(r) : "f"(a));
    return r;
}
__device__ __forceinline__ float2 upk(unsigned long long v) {
    float2 f;
    asm("mov.b64 {%0, %1}, %2;" : "=f"(f.x), "=f"(f.y) : "l"(v));
    return f;
}

// ---------------- K1: zero init ----------------
__global__ void k_init(float* out) {
    int i = blockIdx.x * 256 + threadIdx.x;
    if (i < 98304) out[i] = 0.f;            // adj_new (65536) + h (32768)
    if (i < NN) g_deg[i] = 0;
    if (i < 64) g_bk_cnt[i] = 0;
    if (i < 8192) g_G[i] = 0.f;
    if (i == 0) g_sumA2 = 0u;
}

// ---------------- K2: histograms (shared-mem aggregated for the 64 buckets) ----
__global__ __launch_bounds__(256) void k_hist(const int* __restrict__ ei,
                                              const int* __restrict__ batch) {
    __shared__ int h[64];
    int t = threadIdx.x;
    if (t < 64) h[t] = 0;
    __syncthreads();
    for (int i = blockIdx.x * 256 + t; i < EE; i += gridDim.x * 256) {
        int s = ei[i], d = ei[EE + i];
        atomicAdd(&g_deg[d], 1);
        atomicAdd(&h[batch[s] * 8 + batch[d]], 1);
    }
    __syncthreads();
    if (t < 64 && h[t]) atomicAdd(&g_bk_cnt[t], h[t]);
}

// ---------------- K3: exclusive scans (single block) ----------------
__global__ void k_scan() {
    __shared__ int part[1024];
    int t = threadIdx.x;
    int base = t * 12;
    int loc[12]; int s = 0;
    #pragma unroll
    for (int i = 0; i < 12; i++) { loc[i] = s; s += g_deg[base + i]; }
    part[t] = s;
    __syncthreads();
    for (int d = 1; d < 1024; d <<= 1) {
        int v = (t >= d) ? part[t - d] : 0;
        __syncthreads();
        part[t] += v;
        __syncthreads();
    }
    int pre = t ? part[t - 1] : 0;
    #pragma unroll
    for (int i = 0; i < 12; i++) {
        int o = pre + loc[i];
        g_off[base + i] = o;
        g_cur[base + i] = o;
    }
    if (t == 0) {
        int acc = 0;
        for (int k = 0; k < 64; k++) {
            g_bk_off[k] = acc; g_bk_cur[k] = acc; acc += g_bk_cnt[k];
        }
    }
}

// ---------------- K4: scatter (bucket scatter via block-local ranking) --------
__global__ __launch_bounds__(1024) void k_scatter(const int* __restrict__ ei,
                                                  const int* __restrict__ batch) {
    __shared__ int cnt[64];
    __shared__ int base[64];
    int t = threadIdx.x;
    if (t < 64) cnt[t] = 0;
    __syncthreads();
    int i = blockIdx.x * 1024 + t;          // EE == 192 * 1024 exactly
    int s = ei[i], d = ei[EE + i];
    int key = batch[s] * 8 + batch[d];
    int rank = atomicAdd(&cnt[key], 1);
    int p = atomicAdd(&g_cur[d], 1);
    g_src_by_dst[p] = s;
    __syncthreads();
    if (t < 64) base[t] = cnt[t] ? atomicAdd(&g_bk_cur[t], cnt[t]) : 0;
    __syncthreads();
    int q = base[key] + rank;
    g_eb_src[q] = s;
    g_eb_dst[q] = d;
}

// ---------------- K5: mean aggregation (warp per dst node) ----------------
__global__ __launch_bounds__(256) void k_agg(const float* __restrict__ x) {
    int t = threadIdx.x, w = t >> 5, lane = t & 31;
    int n = blockIdx.x * 8 + w;
    int e0 = g_off[n], deg = g_deg[n];
    float4 a = make_float4(0.f, 0.f, 0.f, 0.f);
    for (int e = e0; e < e0 + deg; e++) {
        int s = g_src_by_dst[e];
        float4 v = *(const float4*)(x + (size_t)s * FF + lane * 4);
        a.x += v.x; a.y += v.y; a.z += v.z; a.w += v.w;
    }
    float inv = 1.f / fmaxf((float)deg, 1.f);
    a.x *= inv; a.y *= inv; a.z *= inv; a.w *= inv;
    *(float4*)(g_agg + (size_t)n * FF + lane * 4) = a;
}

// ---------------- K6: GEMM  [N x 256] @ [256 x 384] with packed f32x2 FMA ----
// BM=64, BN=128, BK=16. 256 threads: tm=t>>4 (4 rows), tn=t&15 (8 cols = 4 pairs).
__global__ __launch_bounds__(256) void k_gemm(const float* __restrict__ x,
                                              const float* __restrict__ Wembd,
                                              const float* __restrict__ Wpool) {
    __shared__ float As[16][64];
    __shared__ float Bs[16][128];
    int t = threadIdx.x;
    int row0 = blockIdx.x * 64;
    int cb = blockIdx.y;                 // 0: embd cols, 1/2: pool cols
    const float* W = (cb == 0) ? Wembd : Wpool;
    int ldw  = (cb == 0) ? 128 : 256;
    int wofs = (cb == 0) ? 0 : (cb - 1) * 128;
    int tm = t >> 4, tn = t & 15;

    unsigned long long acc[4][4];
    #pragma unroll
    for (int r = 0; r < 4; r++)
        #pragma unroll
        for (int p = 0; p < 4; p++) acc[r][p] = 0ull;

    for (int kc = 0; kc < 256; kc += 16) {
        {   // A tile: 16x64, 4 floats per thread
            int r = t & 63, kq = (t >> 6) * 4;
            const float* Asrc = (kc < 128) ? x : g_agg;
            int kk = kc & 127;
            float4 v = *(const float4*)(Asrc + (size_t)(row0 + r) * FF + kk + kq);
            As[kq + 0][r] = v.x; As[kq + 1][r] = v.y;
            As[kq + 2][r] = v.z; As[kq + 3][r] = v.w;
        }
        {   // B tile: 16x128, 8 floats per thread
            int kr = t >> 4, nq = (t & 15) * 8;
            const float* wp = W + (size_t)(kc + kr) * ldw + wofs + nq;
            *(float4*)&Bs[kr][nq]     = *(const float4*)wp;
            *(float4*)&Bs[kr][nq + 4] = *(const float4*)(wp + 4);
        }
        __syncthreads();
        #pragma unroll
        for (int k = 0; k < 16; k++) {
            float4 a4 = *(const float4*)&As[k][tm * 4];
            const ulonglong2* bp = (const ulonglong2*)&Bs[k][tn * 8];
            ulonglong2 b01 = bp[0];
            ulonglong2 b23 = bp[1];
            unsigned long long a0 = pkdup(a4.x), a1 = pkdup(a4.y);
            unsigned long long a2 = pkdup(a4.z), a3 = pkdup(a4.w);
            ffma2(acc[0][0], a0, b01.x); ffma2(acc[0][1], a0, b01.y);
            ffma2(acc[0][2], a0, b23.x); ffma2(acc[0][3], a0, b23.y);
            ffma2(acc[1][0], a1, b01.x); ffma2(acc[1][1], a1, b01.y);
            ffma2(acc[1][2], a1, b23.x); ffma2(acc[1][3], a1, b23.y);
            ffma2(acc[2][0], a2, b01.x); ffma2(acc[2][1], a2, b01.y);
            ffma2(acc[2][2], a2, b23.x); ffma2(acc[2][3], a2, b23.y);
            ffma2(acc[3][0], a3, b01.x); ffma2(acc[3][1], a3, b01.y);
            ffma2(acc[3][2], a3, b23.x); ffma2(acc[3][3], a3, b23.y);
        }
        __syncthreads();
    }
    #pragma unroll
    for (int r = 0; r < 4; r++) {
        float2 f0 = upk(acc[r][0]), f1 = upk(acc[r][1]);
        float2 f2 = upk(acc[r][2]), f3 = upk(acc[r][3]);
        float* dst = g_lin + (size_t)(row0 + tm * 4 + r) * 384 + cb * 128 + tn * 8;
        *(float4*)dst       = make_float4(f0.x, f0.y, f1.x, f1.y);
        *(float4*)(dst + 4) = make_float4(f2.x, f2.y, f3.x, f3.y);
    }
}

// ---------------- K7: bias + L2-normalize + block softmax (warp per node) ----
__global__ __launch_bounds__(256) void k_epi(const float* __restrict__ bembd,
                                             const float* __restrict__ bpool,
                                             const int* __restrict__ batch) {
    __shared__ float sblk[8][32];
    int t = threadIdx.x, w = t >> 5, lane = t & 31;
    int n = blockIdx.x * 8 + w;
    const float* L = g_lin + (size_t)n * 384;

    // embed part (lin cols 0..127)
    float4 v = *(const float4*)(L + lane * 4);
    float4 be = *(const float4*)(bembd + lane * 4);
    v.x += be.x; v.y += be.y; v.z += be.z; v.w += be.w;
    float ss = wsum(v.x * v.x + v.y * v.y + v.z * v.z + v.w * v.w);
    float inv = 1.f / fmaxf(sqrtf(ss), 1e-12f);
    float4 e4 = make_float4(v.x * inv, v.y * inv, v.z * inv, v.w * inv);
    *(float4*)(g_embed + (size_t)n * FF + lane * 4) = e4;

    // pool part (lin cols 128..383): lane holds pooled cols [lane*8, lane*8+8)
    float4 p0 = *(const float4*)(L + 128 + lane * 8);
    float4 p1 = *(const float4*)(L + 128 + lane * 8 + 4);
    float4 b0 = *(const float4*)(bpool + lane * 8);
    float4 b1 = *(const float4*)(bpool + lane * 8 + 4);
    p0.x += b0.x; p0.y += b0.y; p0.z += b0.z; p0.w += b0.w;
    p1.x += b1.x; p1.y += b1.y; p1.z += b1.z; p1.w += b1.w;
    float ss2 = wsum(p0.x * p0.x + p0.y * p0.y + p0.z * p0.z + p0.w * p0.w +
                     p1.x * p1.x + p1.y * p1.y + p1.z * p1.z + p1.w * p1.w);
    float inv2 = 1.f / fmaxf(sqrtf(ss2), 1e-12f);

    int g = batch[n];
    if ((lane >> 2) == g) {
        int off = (lane & 3) * 8;
        sblk[w][off + 0] = p0.x * inv2; sblk[w][off + 1] = p0.y * inv2;
        sblk[w][off + 2] = p0.z * inv2; sblk[w][off + 3] = p0.w * inv2;
        sblk[w][off + 4] = p1.x * inv2; sblk[w][off + 5] = p1.y * inv2;
        sblk[w][off + 6] = p1.z * inv2; sblk[w][off + 7] = p1.w * inv2;
    }
    __syncwarp();
    float m = sblk[w][lane];
    float mx = wmax(m);
    float e = __expf(m - mx);
    float s = wsum(e);
    g_result[(size_t)n * 32 + lane] = e / s;
}

// ---------------- K8: adj_new = sum_edges outer(S[src], S[dst]) ----------------
__global__ __launch_bounds__(256) void k_adj(float* out) {
    int b = blockIdx.x;
    int s0 = g_bk_off[b];
    int s1 = (b == 63) ? EE : g_bk_off[b + 1];
    int len = s1 - s0;
    int per = (len + 7) / 8;
    int e0 = s0 + blockIdx.y * per;
    int e1 = min(e0 + per, s1);
    __shared__ float Sa[8][32];
    __shared__ float Sb[8][32];
    int t = threadIdx.x;
    int i = t >> 3, j0 = (t & 7) * 4;
    float4 acc = make_float4(0.f, 0.f, 0.f, 0.f);
    for (int base = e0; base < e1; base += 8) {
        int ne = min(8, e1 - base);
        if ((t >> 5) < ne) {
            int e = base + (t >> 5);
            int l = t & 31;
            Sa[t >> 5][l] = g_result[(size_t)g_eb_src[e] * 32 + l];
            Sb[t >> 5][l] = g_result[(size_t)g_eb_dst[e] * 32 + l];
        }
        __syncthreads();
        for (int jj = 0; jj < ne; jj++) {
            float a = Sa[jj][i];
            float4 bv = *(const float4*)&Sb[jj][j0];
            acc.x += a * bv.x; acc.y += a * bv.y;
            acc.z += a * bv.z; acc.w += a * bv.w;
        }
        __syncthreads();
    }
    if (e0 < e1) {
        int gs = b >> 3, gd = b & 7;
        float* dst = out + (size_t)(gs * 32 + i) * 256 + gd * 32 + j0;
        atomicAdd(dst + 0, acc.x); atomicAdd(dst + 1, acc.y);
        atomicAdd(dst + 2, acc.z); atomicAdd(dst + 3, acc.w);
    }
}

// ---------------- K9: h = S^T E  and  G = S^T S  (per graph) ----------------
__global__ __launch_bounds__(256) void k_pool(const int* __restrict__ batch, float* out) {
    __shared__ float Ms[4][160];
    __shared__ int srange[2];
    int g = blockIdx.x;
    int t = threadIdx.x;
    if (t == 0) { srange[0] = lbound(batch, g); srange[1] = lbound(batch, g + 1); }
    __syncthreads();
    int n0 = srange[0], n1 = srange[1];
    int len = n1 - n0;
    int per = (len + 15) / 16;
    int m0 = n0 + blockIdx.y * per;
    int m1 = min(m0 + per, n1);

    int i = t >> 3, j0 = (t & 7) * 4;
    float4 acc[5];
    #pragma unroll
    for (int b = 0; b < 5; b++) acc[b] = make_float4(0.f, 0.f, 0.f, 0.f);

    for (int base = m0; base < m1; base += 4) {
        int nn = min(4, m1 - base);
        for (int idx = t; idx < nn * 160; idx += 256) {
            int j = idx / 160, c = idx % 160;
            int n = base + j;
            Ms[j][c] = (c < 128) ? g_embed[(size_t)n * 128 + c]
                                 : g_result[(size_t)n * 32 + (c - 128)];
        }
        __syncthreads();
        for (int jj = 0; jj < nn; jj++) {
            float a = Ms[jj][128 + i];
            #pragma unroll
            for (int b = 0; b < 5; b++) {
                float4 v = *(const float4*)&Ms[jj][j0 + 32 * b];
                acc[b].x += a * v.x; acc[b].y += a * v.y;
                acc[b].z += a * v.z; acc[b].w += a * v.w;
            }
        }
        __syncthreads();
    }
    if (m0 < m1) {
        #pragma unroll
        for (int b = 0; b < 4; b++) {
            float* dst = out + 65536 + (size_t)(g * 32 + i) * 128 + j0 + 32 * b;
            atomicAdd(dst + 0, acc[b].x); atomicAdd(dst + 1, acc[b].y);
            atomicAdd(dst + 2, acc[b].z); atomicAdd(dst + 3, acc[b].w);
        }
        float* dg = g_G + (size_t)g * 1024 + i * 32 + j0;
        atomicAdd(dg + 0, acc[4].x); atomicAdd(dg + 1, acc[4].y);
        atomicAdd(dg + 2, acc[4].z); atomicAdd(dg + 3, acc[4].w);
    }
}

// ---------------- K10: sum of squared edge multiplicities (exact, int) --------
__global__ void k_dup() {
    int n = blockIdx.x * 256 + threadIdx.x;
    int cnt = 0;
    if (n < NN) {
        int o = g_off[n], L = g_deg[n];
        for (int ii = 0; ii < L; ii++) {
            int si = g_src_by_dst[o + ii];
            for (int jj = 0; jj < L; jj++) cnt += (g_src_by_dst[o + jj] == si);
        }
    }
    #pragma unroll
    for (int off = 16; off; off >>= 1) cnt += __shfl_xor_sync(0xffffffffu, cnt, off);
    if ((threadIdx.x & 31) == 0) atomicAdd(&g_sumA2, (unsigned int)cnt);
}

// ---------------- K11: finalize losses ----------------
__global__ void k_final(float* out) {
    __shared__ float red[256];
    int t = threadIdx.x;
    float v = out[(size_t)t * 257];          // trace(adj_new)
    red[t] = v;
    __syncthreads();
    for (int s = 128; s; s >>= 1) { if (t < s) red[t] += red[t + s]; __syncthreads(); }
    float tr = red[0];
    __syncthreads();
    float gq = 0.f;                          // ||G||_F^2
    for (int i = t; i < 8192; i += 256) { float g = g_G[i]; gq += g * g; }
    red[t] = gq;
    __syncthreads();
    for (int s = 128; s; s >>= 1) { if (t < s) red[t] += red[t + s]; __syncthreads(); }
    if (t == 0) {
        float a2 = (float)g_sumA2;
        float val = a2 - 2.f * tr + red[0];
        out[98304] = sqrtf(fmaxf(val, 0.f)) / 150994944.0f;   // / N^2
        out[98305] = 12288.0f * logf(32.0f);
    }
}

// ---------------- launch ----------------
extern "C" void kernel_launch(void* const* d_in, const int* in_sizes, int n_in,
                              void* d_out, int out_size) {
    const float* x     = (const float*)d_in[0];
    const int*   ei    = (const int*)d_in[1];
    const int*   batch = (const int*)d_in[2];
    const float* Wembd = (const float*)d_in[3];
    const float* bembd = (const float*)d_in[4];
    const float* Wpool = (const float*)d_in[5];
    const float* bpool = (const float*)d_in[6];
    float* out = (float*)d_out;

    k_init<<<384, 256>>>(out);
    k_hist<<<96, 256>>>(ei, batch);
    k_scan<<<1, 1024>>>();
    k_scatter<<<192, 1024>>>(ei, batch);
    k_agg<<<1536, 256>>>(x);
    k_gemm<<<dim3(192, 3), 256>>>(x, Wembd, Wpool);
    k_epi<<<1536, 256>>>(bembd, bpool, batch);
    k_adj<<<dim3(64, 8), 256>>>(out);
    k_pool<<<dim3(8, 16), 256>>>(batch, out);
    k_dup<<<48, 256>>>();
    k_final<<<1, 256>>>(out);
}

// round 6
// speedup vs baseline: 2.2654x; 1.3226x over previous
#include <cuda_runtime.h>
#include <math.h>

#define NN 12288
#define EE 196608
#define FF 128

// ---------------- static device scratch ----------------
__device__ int   g_deg[NN];
__device__ int   g_off[NN];
__device__ int   g_cur[NN];
__device__ int   g_src_by_dst[EE];
__device__ int   g_bk_cnt[64];
__device__ int   g_bk_off[64];
__device__ int   g_bk_cur[64];
__device__ int   g_eb_src[EE];
__device__ int   g_eb_dst[EE];
__device__ float g_embed[NN * FF];
__device__ float g_result[NN * 32];
__device__ float g_G[8 * 32 * 32];
__device__ unsigned int g_sumA2;

// ---------------- helpers ----------------
__device__ __forceinline__ float wsum(float v) {
    #pragma unroll
    for (int o = 16; o; o >>= 1) v += __shfl_xor_sync(0xffffffffu, v, o);
    return v;
}
__device__ __forceinline__ float wmax(float v) {
    #pragma unroll
    for (int o = 16; o; o >>= 1) v = fmaxf(v, __shfl_xor_sync(0xffffffffu, v, o));
    return v;
}
__device__ __forceinline__ int lbound(const int* b, int v) {
    int lo = 0, hi = NN;
    while (lo < hi) { int m = (lo + hi) >> 1; if (b[m] < v) lo = m + 1; else hi = m; }
    return lo;
}
__device__ __forceinline__ void ffma2(unsigned long long &c, unsigned long long a,
                                      unsigned long long b) {
    asm("fma.rn.f32x2 %0, %1, %2, %0;" : "+l"(c) : "l"(a), "l"(b));
}
__device__ __forceinline__ unsigned long long pkdup(float a) {
    unsigned long long r;
    asm("mov.b64 %0, {%1, %1};" : "=l"(r) : "f"(a));
    return r;
}
__device__ __forceinline__ float2 upk(unsigned long long v) {
    float2 f;
    asm("mov.b64 {%0, %1}, %2;" : "=f"(f.x), "=f"(f.y) : "l"(v));
    return f;
}

// ---------------- K1: zero init ----------------
__global__ void k_init(float* out) {
    int i = blockIdx.x * 256 + threadIdx.x;
    if (i < 98304) out[i] = 0.f;            // adj_new (65536) + h (32768)
    if (i < NN) g_deg[i] = 0;
    if (i < 64) g_bk_cnt[i] = 0;
    if (i < 8192) g_G[i] = 0.f;
    if (i == 0) g_sumA2 = 0u;
}

// ---------------- K2: histograms ----------------
__global__ __launch_bounds__(256) void k_hist(const int* __restrict__ ei,
                                              const int* __restrict__ batch) {
    __shared__ int h[64];
    int t = threadIdx.x;
    if (t < 64) h[t] = 0;
    __syncthreads();
    for (int i = blockIdx.x * 256 + t; i < EE; i += gridDim.x * 256) {
        int s = ei[i], d = ei[EE + i];
        atomicAdd(&g_deg[d], 1);
        atomicAdd(&h[batch[s] * 8 + batch[d]], 1);
    }
    __syncthreads();
    if (t < 64 && h[t]) atomicAdd(&g_bk_cnt[t], h[t]);
}

// ---------------- K3: exclusive scan (shfl-based, 2 barriers) ----------------
__global__ void k_scan() {
    __shared__ int wsums[32];
    int t = threadIdx.x, lane = t & 31, w = t >> 5;
    int base = t * 12;
    int loc[12]; int s = 0;
    #pragma unroll
    for (int i = 0; i < 12; i++) { loc[i] = s; s += g_deg[base + i]; }
    int v = s;
    #pragma unroll
    for (int o = 1; o < 32; o <<= 1) {
        int u = __shfl_up_sync(0xffffffffu, v, o);
        if (lane >= o) v += u;
    }
    if (lane == 31) wsums[w] = v;
    __syncthreads();
    if (w == 0) {
        int u = wsums[lane];
        #pragma unroll
        for (int o = 1; o < 32; o <<= 1) {
            int z = __shfl_up_sync(0xffffffffu, u, o);
            if (lane >= o) u += z;
        }
        wsums[lane] = u;
    }
    __syncthreads();
    int pre = (v - s) + (w ? wsums[w - 1] : 0);
    #pragma unroll
    for (int i = 0; i < 12; i++) {
        int o = pre + loc[i];
        g_off[base + i] = o;
        g_cur[base + i] = o;
    }
    if (t == 0) {
        int acc = 0;
        for (int k = 0; k < 64; k++) {
            g_bk_off[k] = acc; g_bk_cur[k] = acc; acc += g_bk_cnt[k];
        }
    }
}

// ---------------- K4: scatter (block-local bucket ranking) ----------------
__global__ __launch_bounds__(1024) void k_scatter(const int* __restrict__ ei,
                                                  const int* __restrict__ batch) {
    __shared__ int cnt[64];
    __shared__ int base[64];
    int t = threadIdx.x;
    if (t < 64) cnt[t] = 0;
    __syncthreads();
    int i = blockIdx.x * 1024 + t;          // EE == 192 * 1024 exactly
    int s = ei[i], d = ei[EE + i];
    int key = batch[s] * 8 + batch[d];
    int rank = atomicAdd(&cnt[key], 1);
    int p = atomicAdd(&g_cur[d], 1);
    g_src_by_dst[p] = s;
    __syncthreads();
    if (t < 64) base[t] = cnt[t] ? atomicAdd(&g_bk_cur[t], cnt[t]) : 0;
    __syncthreads();
    int q = base[key] + rank;
    g_eb_src[q] = s;
    g_eb_dst[q] = d;
}

// ---------------- K5: fused aggregate + GEMM + epilogue ----------------
// 32 rows per block, 256 threads (8 warps); warp w owns rows w*4..w*4+3.
// Columns: chunk0 = embed (0..127), chunk1/2 = pool (0..255). Packed f32x2 FMA.
__global__ __launch_bounds__(256, 2) void k_megemm(
    const float* __restrict__ x,
    const float* __restrict__ Wembd, const float* __restrict__ Wpool,
    const float* __restrict__ bembd, const float* __restrict__ bpool,
    const int* __restrict__ batch)
{
    __shared__ float aggT[128][36];   // transposed agg for this block's 32 rows
    __shared__ float As[16][36];      // staged x-transpose per k-chunk
    __shared__ float Bs[16][388];     // staged weight chunk (384 cols + pad)
    int t = threadIdx.x, lane = t & 31, w = t >> 5;
    int row0 = blockIdx.x * 32;

    // ---- phase 1: mean-aggregate 4 nodes per warp, write transposed ----
    #pragma unroll
    for (int q = 0; q < 4; q++) {
        int r = w * 4 + q;
        int n = row0 + r;
        int e0 = g_off[n], deg = g_deg[n];
        float4 a = make_float4(0.f, 0.f, 0.f, 0.f);
        for (int b0 = 0; b0 < deg; b0 += 32) {
            int rem = deg - b0;
            int idx = (lane < rem) ? g_src_by_dst[e0 + b0 + lane] : 0;
            int m = rem < 32 ? rem : 32;
            for (int j = 0; j < m; j++) {
                int sN = __shfl_sync(0xffffffffu, idx, j);
                float4 xv = *(const float4*)(x + (size_t)sN * FF + lane * 4);
                a.x += xv.x; a.y += xv.y; a.z += xv.z; a.w += xv.w;
            }
        }
        float inv = 1.f / fmaxf((float)deg, 1.f);
        aggT[lane * 4 + 0][r] = a.x * inv;
        aggT[lane * 4 + 1][r] = a.y * inv;
        aggT[lane * 4 + 2][r] = a.z * inv;
        aggT[lane * 4 + 3][r] = a.w * inv;
    }
    __syncthreads();

    // ---- phase 2: GEMM ----
    unsigned long long acc[4][3][2];
    #pragma unroll
    for (int r = 0; r < 4; r++)
        #pragma unroll
        for (int c = 0; c < 3; c++) { acc[r][c][0] = 0ull; acc[r][c][1] = 0ull; }

    for (int kc = 0; kc < 256; kc += 16) {
        if (kc < 128 && t < 128) {      // stage x chunk transposed
            int r = t & 31, kq = (t >> 5) * 4;
            float4 v = *(const float4*)(x + (size_t)(row0 + r) * FF + kc + kq);
            As[kq + 0][r] = v.x; As[kq + 1][r] = v.y;
            As[kq + 2][r] = v.z; As[kq + 3][r] = v.w;
        }
        {                               // stage B chunk: 16 x 384
            int kr = t >> 4, cb = (t & 15) * 4;
            const float* we = Wembd + (size_t)(kc + kr) * 128;
            const float* wp = Wpool + (size_t)(kc + kr) * 256;
            *(float4*)&Bs[kr][cb]       = *(const float4*)(we + cb);
            *(float4*)&Bs[kr][cb + 64]  = *(const float4*)(we + cb + 64);
            *(float4*)&Bs[kr][cb + 128] = *(const float4*)(wp + cb);
            *(float4*)&Bs[kr][cb + 192] = *(const float4*)(wp + cb + 64);
            *(float4*)&Bs[kr][cb + 256] = *(const float4*)(wp + cb + 128);
            *(float4*)&Bs[kr][cb + 320] = *(const float4*)(wp + cb + 192);
        }
        __syncthreads();
        const float (*Ap)[36] = (kc < 128) ? (const float(*)[36])As
                                           : (const float(*)[36])(aggT + (kc - 128));
        #pragma unroll
        for (int k = 0; k < 16; k++) {
            float4 a4 = *(const float4*)&Ap[k][w * 4];   // warp-broadcast
            unsigned long long a0 = pkdup(a4.x), a1 = pkdup(a4.y);
            unsigned long long a2 = pkdup(a4.z), a3 = pkdup(a4.w);
            #pragma unroll
            for (int c = 0; c < 3; c++) {
                ulonglong2 b = *(const ulonglong2*)&Bs[k][c * 128 + lane * 4];
                ffma2(acc[0][c][0], a0, b.x); ffma2(acc[0][c][1], a0, b.y);
                ffma2(acc[1][c][0], a1, b.x); ffma2(acc[1][c][1], a1, b.y);
                ffma2(acc[2][c][0], a2, b.x); ffma2(acc[2][c][1], a2, b.y);
                ffma2(acc[3][c][0], a3, b.x); ffma2(acc[3][c][1], a3, b.y);
            }
        }
        __syncthreads();
    }

    // ---- phase 3: epilogue (bias, norms, block softmax) ----
    float4 be  = *(const float4*)(bembd + lane * 4);
    float4 bp0 = *(const float4*)(bpool + lane * 4);
    float4 bp1 = *(const float4*)(bpool + 128 + lane * 4);
    #pragma unroll
    for (int r = 0; r < 4; r++) {
        int n = row0 + w * 4 + r;
        int g = batch[n];
        float2 e0 = upk(acc[r][0][0]), e1 = upk(acc[r][0][1]);
        float4 v = make_float4(e0.x + be.x, e0.y + be.y, e1.x + be.z, e1.y + be.w);
        float ss = wsum(v.x * v.x + v.y * v.y + v.z * v.z + v.w * v.w);
        float inv = 1.f / fmaxf(sqrtf(ss), 1e-12f);
        *(float4*)(g_embed + (size_t)n * FF + lane * 4) =
            make_float4(v.x * inv, v.y * inv, v.z * inv, v.w * inv);

        float2 q0 = upk(acc[r][1][0]), q1 = upk(acc[r][1][1]);
        float2 q2 = upk(acc[r][2][0]), q3 = upk(acc[r][2][1]);
        float4 P0 = make_float4(q0.x + bp0.x, q0.y + bp0.y, q1.x + bp0.z, q1.y + bp0.w);
        float4 P1 = make_float4(q2.x + bp1.x, q2.y + bp1.y, q3.x + bp1.z, q3.y + bp1.w);
        float ss2 = wsum(P0.x * P0.x + P0.y * P0.y + P0.z * P0.z + P0.w * P0.w +
                         P1.x * P1.x + P1.y * P1.y + P1.z * P1.z + P1.w * P1.w);
        float inv2 = 1.f / fmaxf(sqrtf(ss2), 1e-12f);

        float4 M = (g < 4) ? P0 : P1;
        bool own = (lane >> 3) == (g & 3);
        float m0 = M.x * inv2, m1 = M.y * inv2, m2 = M.z * inv2, m3 = M.w * inv2;
        float loc = own ? fmaxf(fmaxf(m0, m1), fmaxf(m2, m3)) : -1e30f;
        float mx = wmax(loc);
        float ex0 = 0.f, ex1 = 0.f, ex2 = 0.f, ex3 = 0.f;
        if (own) {
            ex0 = __expf(m0 - mx); ex1 = __expf(m1 - mx);
            ex2 = __expf(m2 - mx); ex3 = __expf(m3 - mx);
        }
        float s = wsum(ex0 + ex1 + ex2 + ex3);
        if (own) {
            float is = 1.f / s;
            *(float4*)(g_result + (size_t)n * 32 + (lane & 7) * 4) =
                make_float4(ex0 * is, ex1 * is, ex2 * is, ex3 * is);
        }
    }
}

// ---------------- K6: merged post (adj 512 | pool 128 | dup 48 blocks) -------
__global__ __launch_bounds__(256) void k_post(const int* __restrict__ batch, float* out) {
    __shared__ float shf[640];
    __shared__ int srange[2];
    int b = blockIdx.x;
    int t = threadIdx.x;

    if (b < 512) {
        // ---- adj_new = sum_edges outer(S[src], S[dst]) ----
        int bk = b & 63, split = b >> 6;
        int s0 = g_bk_off[bk];
        int s1 = (bk == 63) ? EE : g_bk_off[bk + 1];
        int len = s1 - s0;
        int per = (len + 7) / 8;
        int e0 = s0 + split * per;
        int e1 = min(e0 + per, s1);
        float (*Sa)[32] = (float(*)[32])shf;
        float (*Sb)[32] = (float(*)[32])(shf + 256);
        int i = t >> 3, j0 = (t & 7) * 4;
        float4 acc = make_float4(0.f, 0.f, 0.f, 0.f);
        for (int base = e0; base < e1; base += 8) {
            int ne = min(8, e1 - base);
            if ((t >> 5) < ne) {
                int e = base + (t >> 5);
                int l = t & 31;
                Sa[t >> 5][l] = g_result[(size_t)g_eb_src[e] * 32 + l];
                Sb[t >> 5][l] = g_result[(size_t)g_eb_dst[e] * 32 + l];
            }
            __syncthreads();
            for (int jj = 0; jj < ne; jj++) {
                float a = Sa[jj][i];
                float4 bv = *(const float4*)&Sb[jj][j0];
                acc.x += a * bv.x; acc.y += a * bv.y;
                acc.z += a * bv.z; acc.w += a * bv.w;
            }
            __syncthreads();
        }
        if (e0 < e1) {
            int gs = bk >> 3, gd = bk & 7;
            float* dst = out + (size_t)(gs * 32 + i) * 256 + gd * 32 + j0;
            atomicAdd(dst + 0, acc.x); atomicAdd(dst + 1, acc.y);
            atomicAdd(dst + 2, acc.z); atomicAdd(dst + 3, acc.w);
        }
    } else if (b < 640) {
        // ---- h = S^T E and G = S^T S (per graph) ----
        int pb = b - 512;
        int g = pb & 7, split = pb >> 3;
        float (*Ms)[160] = (float(*)[160])shf;
        if (t == 0) { srange[0] = lbound(batch, g); srange[1] = lbound(batch, g + 1); }
        __syncthreads();
        int n0 = srange[0], n1 = srange[1];
        int len = n1 - n0;
        int per = (len + 15) / 16;
        int m0 = n0 + split * per;
        int m1 = min(m0 + per, n1);
        int i = t >> 3, j0 = (t & 7) * 4;
        float4 acc[5];
        #pragma unroll
        for (int c = 0; c < 5; c++) acc[c] = make_float4(0.f, 0.f, 0.f, 0.f);
        for (int base = m0; base < m1; base += 4) {
            int nn = min(4, m1 - base);
            for (int idx = t; idx < nn * 160; idx += 256) {
                int j = idx / 160, c = idx % 160;
                int n = base + j;
                Ms[j][c] = (c < 128) ? g_embed[(size_t)n * 128 + c]
                                     : g_result[(size_t)n * 32 + (c - 128)];
            }
            __syncthreads();
            for (int jj = 0; jj < nn; jj++) {
                float a = Ms[jj][128 + i];
                #pragma unroll
                for (int c = 0; c < 5; c++) {
                    float4 v = *(const float4*)&Ms[jj][j0 + 32 * c];
                    acc[c].x += a * v.x; acc[c].y += a * v.y;
                    acc[c].z += a * v.z; acc[c].w += a * v.w;
                }
            }
            __syncthreads();
        }
        if (m0 < m1) {
            #pragma unroll
            for (int c = 0; c < 4; c++) {
                float* dst = out + 65536 + (size_t)(g * 32 + i) * 128 + j0 + 32 * c;
                atomicAdd(dst + 0, acc[c].x); atomicAdd(dst + 1, acc[c].y);
                atomicAdd(dst + 2, acc[c].z); atomicAdd(dst + 3, acc[c].w);
            }
            float* dg = g_G + (size_t)g * 1024 + i * 32 + j0;
            atomicAdd(dg + 0, acc[4].x); atomicAdd(dg + 1, acc[4].y);
            atomicAdd(dg + 2, acc[4].z); atomicAdd(dg + 3, acc[4].w);
        }
    } else {
        // ---- sum of squared edge multiplicities (exact, int) ----
        int n = (b - 640) * 256 + t;
        int cnt = 0;
        if (n < NN) {
            int o = g_off[n], L = g_deg[n];
            for (int ii = 0; ii < L; ii++) {
                int si = g_src_by_dst[o + ii];
                for (int jj = 0; jj < L; jj++) cnt += (g_src_by_dst[o + jj] == si);
            }
        }
        #pragma unroll
        for (int off = 16; off; off >>= 1) cnt += __shfl_xor_sync(0xffffffffu, cnt, off);
        if ((t & 31) == 0) atomicAdd(&g_sumA2, (unsigned int)cnt);
    }
}

// ---------------- K7: finalize losses ----------------
__global__ void k_final(float* out) {
    __shared__ float red[256];
    int t = threadIdx.x;
    float v = out[(size_t)t * 257];          // trace(adj_new)
    red[t] = v;
    __syncthreads();
    for (int s = 128; s; s >>= 1) { if (t < s) red[t] += red[t + s]; __syncthreads(); }
    float tr = red[0];
    __syncthreads();
    float gq = 0.f;                          // ||G||_F^2
    for (int i = t; i < 8192; i += 256) { float g = g_G[i]; gq += g * g; }
    red[t] = gq;
    __syncthreads();
    for (int s = 128; s; s >>= 1) { if (t < s) red[t] += red[t + s]; __syncthreads(); }
    if (t == 0) {
        float a2 = (float)g_sumA2;
        float val = a2 - 2.f * tr + red[0];
        out[98304] = sqrtf(fmaxf(val, 0.f)) / 150994944.0f;   // / N^2
        out[98305] = 12288.0f * logf(32.0f);
    }
}

// ---------------- launch ----------------
extern "C" void kernel_launch(void* const* d_in, const int* in_sizes, int n_in,
                              void* d_out, int out_size) {
    const float* x     = (const float*)d_in[0];
    const int*   ei    = (const int*)d_in[1];
    const int*   batch = (const int*)d_in[2];
    const float* Wembd = (const float*)d_in[3];
    const float* bembd = (const float*)d_in[4];
    const float* Wpool = (const float*)d_in[5];
    const float* bpool = (const float*)d_in[6];
    float* out = (float*)d_out;

    k_init<<<384, 256>>>(out);
    k_hist<<<96, 256>>>(ei, batch);
    k_scan<<<1, 1024>>>();
    k_scatter<<<192, 1024>>>(ei, batch);
    k_megemm<<<384, 256>>>(x, Wembd, Wpool, bembd, bpool, batch);
    k_post<<<688, 256>>>(batch, out);
    k_final<<<1, 256>>>(out);
}